// round 1
// baseline (speedup 1.0000x reference)
#include <cuda_runtime.h>
#include <cuda_bf16.h>
#include <math.h>

// Problem constants
#define BSZ 4
#define TLEN 2048
#define CDIM 1024
#define BT (BSZ*TLEN)            // 8192
#define TOT ((long long)BT*CDIM) // 8,388,608
#define NS_ITERS 32

// ---------------- scratch (static device globals; no cudaMalloc allowed) ----
__device__ float g_q0[BT*CDIM];
__device__ float g_q1[BT*CDIM];
__device__ float g_u [BT*CDIM];
__device__ float g_vc[BT*CDIM];
__device__ float g_v [BT*CDIM];
__device__ float g_X0[CDIM*CDIM];
__device__ float g_X1[CDIM*CDIM];
__device__ float g_A [CDIM*CDIM];

// ---------------- generic strided SGEMM ------------------------------------
// C[M,N] (row-major) = alpha * A(MxK) @ B(KxN) + beta * Cin[M,N]
// A element (m,k) at A[m*As_m + k*As_k]; B element (k,n) at B[k*Bs_k + n*Bs_n]
template<int BM,int BN,int BK,int TM,int TN>
__global__ void gemm_kernel(const float* __restrict__ A, const float* __restrict__ B,
                            float* __restrict__ C, const float* __restrict__ Cin,
                            int M, int N, int K,
                            long long As_m, long long As_k,
                            long long Bs_k, long long Bs_n,
                            float alpha, float beta)
{
    constexpr int THREADS = (BM/TM)*(BN/TN);
    __shared__ float As[BK][BM+4];
    __shared__ float Bs[BK][BN+4];
    const int tid = threadIdx.x;
    const int tx  = tid % (BN/TN);
    const int ty  = tid / (BN/TN);
    const int m0  = blockIdx.y * BM;
    const int n0  = blockIdx.x * BN;

    float acc[TM][TN];
    #pragma unroll
    for (int i=0;i<TM;i++)
        #pragma unroll
        for (int j=0;j<TN;j++) acc[i][j] = 0.0f;

    for (int k0 = 0; k0 < K; k0 += BK) {
        // ---- load A tile (pick loader for coalescing) ----
        if (As_k == 1) {
            #pragma unroll
            for (int l = tid; l < BM*BK; l += THREADS) {
                int k = l % BK, m = l / BK;
                As[k][m] = A[(long long)(m0+m)*As_m + (long long)(k0+k)];
            }
        } else {
            #pragma unroll
            for (int l = tid; l < BM*BK; l += THREADS) {
                int m = l % BM, k = l / BM;
                As[k][m] = A[(long long)(m0+m)*As_m + (long long)(k0+k)*As_k];
            }
        }
        // ---- load B tile ----
        if (Bs_n == 1) {
            #pragma unroll
            for (int l = tid; l < BK*BN; l += THREADS) {
                int n = l % BN, k = l / BN;
                Bs[k][n] = B[(long long)(k0+k)*Bs_k + (long long)(n0+n)];
            }
        } else {
            #pragma unroll
            for (int l = tid; l < BK*BN; l += THREADS) {
                int k = l % BK, n = l / BK;
                Bs[k][n] = B[(long long)(k0+k)*Bs_k + (long long)(n0+n)*Bs_n];
            }
        }
        __syncthreads();
        #pragma unroll
        for (int kk = 0; kk < BK; kk++) {
            float ra[TM], rb[TN];
            #pragma unroll
            for (int i=0;i<TM;i++) ra[i] = As[kk][ty*TM+i];
            #pragma unroll
            for (int j=0;j<TN;j++) rb[j] = Bs[kk][tx*TN+j];
            #pragma unroll
            for (int i=0;i<TM;i++)
                #pragma unroll
                for (int j=0;j<TN;j++)
                    acc[i][j] = fmaf(ra[i], rb[j], acc[i][j]);
        }
        __syncthreads();
    }
    // epilogue
    #pragma unroll
    for (int i=0;i<TM;i++) {
        #pragma unroll
        for (int j=0;j<TN;j++) {
            long long idx = (long long)(m0+ty*TM+i)*N + (n0+tx*TN+j);
            float vv = alpha*acc[i][j];
            if (Cin) vv += beta*Cin[idx];
            C[idx] = vv;
        }
    }
}

// ---------------- elementwise kernels ---------------------------------------
__global__ void scale_kernel(const float* __restrict__ src, float* __restrict__ dst,
                             float s, long long n)
{
    long long i = (long long)blockIdx.x*blockDim.x + threadIdx.x;
    if (i < n) dst[i] = src[i]*s;
}

// u[t] = left[t] + cur[t]  with left = identity (tt<d) or cur[t-d]
__global__ void shift_add_kernel(const float* __restrict__ cur,
                                 const float* __restrict__ ident,
                                 float* __restrict__ u, int d)
{
    long long i = (long long)blockIdx.x*blockDim.x + threadIdx.x;
    if (i >= TOT) return;
    long long t = i >> 10;          // / CDIM
    int c  = (int)(i & 1023);
    int tt = (int)(t % TLEN);
    float leftv = (tt >= d) ? cur[i - (long long)d*CDIM] : ident[c];
    u[i] = leftv + cur[i];
}

__global__ void mul_kernel(const float* __restrict__ a, const float* __restrict__ b,
                           float* __restrict__ c)
{
    long long i = (long long)blockIdx.x*blockDim.x + threadIdx.x;
    if (i < TOT) c[i] = a[i]*b[i];
}

// ---------------- combine: tiny 4-lane SDPA + rmsnorm per token -------------
// one block per token, 256 threads (one per hd index), 4 lanes in registers
__global__ void combine_kernel(const float* __restrict__ cur,
                               const float* __restrict__ vc,
                               const float* __restrict__ ident,
                               float* __restrict__ nxt, int d)
{
    const int t  = blockIdx.x;         // 0..BT-1
    const int tt = t % TLEN;
    const int j  = threadIdx.x;        // 0..255
    const float* left  = (tt >= d) ? (cur + (long long)(t-d)*CDIM) : ident;
    const float* right = cur + (long long)t*CDIM;
    const float* vv    = vc  + (long long)t*CDIM;

    float l[4], r[4], w[4];
    #pragma unroll
    for (int i=0;i<4;i++) {
        l[i] = left [i*256 + j];
        r[i] = right[i*256 + j];
        w[i] = vv   [i*256 + j];
    }

    __shared__ float red[16][8];
    __shared__ float scores[16];
    __shared__ float scale_s[4];
    const int lane = j & 31, warp = j >> 5;

    // 16 dot products over 256 dims: scores[a][b] = <left_a, right_b>
    #pragma unroll
    for (int q=0;q<16;q++) {
        float v = l[q>>2] * r[q&3];
        #pragma unroll
        for (int o=16;o>0;o>>=1) v += __shfl_down_sync(0xffffffffu, v, o);
        if (lane==0) red[q][warp] = v;
    }
    __syncthreads();
    if (j < 16) {
        float s = 0.f;
        #pragma unroll
        for (int wq=0;wq<8;wq++) s += red[j][wq];
        scores[j] = s * 0.0625f;    // hd^-0.5 = 1/16
    }
    __syncthreads();

    // softmax per lane row (computed redundantly per thread; tiny)
    float att[4][4];
    #pragma unroll
    for (int a=0;a<4;a++) {
        float mx = scores[a*4];
        #pragma unroll
        for (int b=1;b<4;b++) mx = fmaxf(mx, scores[a*4+b]);
        float sm = 0.f;
        #pragma unroll
        for (int b=0;b<4;b++) { att[a][b] = expf(scores[a*4+b]-mx); sm += att[a][b]; }
        float inv = 1.0f/sm;
        #pragma unroll
        for (int b=0;b<4;b++) att[a][b] *= inv;
    }

    // z[a][j] = sum_m att[a][m] * v[m][j]
    float z[4];
    #pragma unroll
    for (int a=0;a<4;a++)
        z[a] = att[a][0]*w[0] + att[a][1]*w[1] + att[a][2]*w[2] + att[a][3]*w[3];

    __syncthreads();   // red reuse
    #pragma unroll
    for (int a=0;a<4;a++) {
        float v = z[a]*z[a];
        #pragma unroll
        for (int o=16;o>0;o>>=1) v += __shfl_down_sync(0xffffffffu, v, o);
        if (lane==0) red[a][warp] = v;
    }
    __syncthreads();
    if (j < 4) {
        float s = 0.f;
        #pragma unroll
        for (int wq=0;wq<8;wq++) s += red[j][wq];
        scale_s[j] = rsqrtf(s*(1.0f/256.0f) + 1e-8f) / (float)(j+1);
    }
    __syncthreads();

    float* o = nxt + (long long)t*CDIM;
    #pragma unroll
    for (int a=0;a<4;a++)
        o[a*256 + j] = l[a] + z[a]*scale_s[a];
}

// ---------------- host orchestration ----------------------------------------
static inline void gemm128(const float* A, const float* B, float* C, const float* Cin,
                           int M, int N, int K,
                           long long am, long long ak, long long bk, long long bn,
                           float alpha, float beta)
{
    dim3 grid(N/128, M/128);
    gemm_kernel<128,128,16,8,8><<<grid, 256>>>(A,B,C,Cin,M,N,K,am,ak,bk,bn,alpha,beta);
}
static inline void gemm64(const float* A, const float* B, float* C, const float* Cin,
                          int M, int N, int K,
                          long long am, long long ak, long long bk, long long bn,
                          float alpha, float beta)
{
    dim3 grid(N/64, M/64);
    gemm_kernel<64,64,32,4,4><<<grid, 256>>>(A,B,C,Cin,M,N,K,am,ak,bk,bn,alpha,beta);
}

extern "C" void kernel_launch(void* const* d_in, const int* in_sizes, int n_in,
                              void* d_out, int out_size)
{
    const float* x      = (const float*)d_in[0];   // [4,2048,1024]
    const float* W_up   = (const float*)d_in[1];   // [1024,1024]
    const float* W_v    = (const float*)d_in[2];
    const float* W_proj = (const float*)d_in[3];
    const float* ident  = (const float*)d_in[4];   // [1024]
    const float* W_raw  = (const float*)d_in[5];
    float* out = (float*)d_out;                    // (Y, q) concatenated
    const long long half = (long long)out_size / 2;

    float *q0,*q1,*u,*vc,*v,*X0,*X1,*Am;
    cudaGetSymbolAddress((void**)&q0, g_q0);
    cudaGetSymbolAddress((void**)&q1, g_q1);
    cudaGetSymbolAddress((void**)&u , g_u );
    cudaGetSymbolAddress((void**)&vc, g_vc);
    cudaGetSymbolAddress((void**)&v , g_v );
    cudaGetSymbolAddress((void**)&X0, g_X0);
    cudaGetSymbolAddress((void**)&X1, g_X1);
    cudaGetSymbolAddress((void**)&Am, g_A );

    const int C = CDIM;
    const long long WN = (long long)C*C;

    // ---- 1) Newton–Schulz polar factor: W = polar(W_scan_raw) ----
    {
        int nb = (int)((WN + 255)/256);
        scale_kernel<<<nb,256>>>(W_raw, X0, 2.0f/3.0f, WN);  // sigma_max ~0.85 < 1
    }
    float* X  = X0;
    float* Xn = X1;
    for (int it = 0; it < NS_ITERS; it++) {
        // Am = X^T @ X      (A(i,k)=X[k,i] -> As_m=1, As_k=C)
        gemm64(X, X, Am, nullptr, C, C, C, 1, C, C, 1, 1.0f, 0.0f);
        // Xn = 1.5*X - 0.5*(X @ Am)
        gemm64(X, Am, Xn, X, C, C, C, C, 1, C, 1, -0.5f, 1.5f);
        float* tmp = X; X = Xn; Xn = tmp;
    }
    const float* W = X;

    // ---- 2) q0 = x @ W_up^T ; v = x @ W_v^T  (B[k,n] = Wm[n*C+k]) ----
    gemm128(x, W_up, q0, nullptr, BT, C, C, C, 1, 1, C, 1.0f, 0.0f);
    gemm128(x, W_v , v , nullptr, BT, C, C, C, 1, 1, C, 1.0f, 0.0f);

    // ---- 3) parallel scan: 11 Hillis-Steele steps ----
    float* cur = q0;
    float* nxt = q1;
    const int ew_blocks = (int)((TOT + 255)/256);
    for (int d = 1; d < TLEN; d <<= 1) {
        shift_add_kernel<<<ew_blocks,256>>>(cur, ident, u, d);
        // vc = u @ W   (NN, W row-major)
        gemm128(u, W, vc, nullptr, BT, C, C, C, 1, C, 1, 1.0f, 0.0f);
        combine_kernel<<<BT,256>>>(cur, vc, ident, nxt, d);
        float* tmp = cur; cur = nxt; nxt = tmp;
    }

    // ---- 4) Y = (q*v) @ W_proj^T ; write (Y, q) ----
    mul_kernel<<<ew_blocks,256>>>(cur, v, u);
    gemm128(u, W_proj, out, nullptr, BT, C, C, C, 1, 1, C, 1.0f, 0.0f);
    cudaMemcpyAsync(out + half, cur, half*sizeof(float), cudaMemcpyDeviceToDevice, 0);
}

// round 4
// speedup vs baseline: 3.9775x; 3.9775x over previous
#include <cuda_runtime.h>
#include <cuda_bf16.h>
#include <cstdint>
#include <math.h>

#define BSZ 4
#define TLEN 2048
#define CDIM 1024
#define BT (BSZ*TLEN)            // 8192
#define TOT ((long long)BT*CDIM)
#define NS_ITERS 32

// ---------------- scratch (device globals; no cudaMalloc allowed) ----------
__device__ float g_q0[BT*CDIM];
__device__ float g_q1[BT*CDIM];
__device__ float g_vc[BT*CDIM];
__device__ float g_v [BT*CDIM];
__device__ float g_X0[CDIM*CDIM];
__device__ float g_X1[CDIM*CDIM];
__device__ float g_Am[CDIM*CDIM];
__device__ __nv_bfloat16 g_ga_hi[BT*CDIM],   g_ga_lo[BT*CDIM];
__device__ __nv_bfloat16 g_gb_hi[CDIM*CDIM], g_gb_lo[CDIM*CDIM];
__device__ __nv_bfloat16 g_wt_hi[CDIM*CDIM], g_wt_lo[CDIM*CDIM];
__device__ __nv_bfloat16 g_xt_hi[CDIM*CDIM], g_xt_lo[CDIM*CDIM];
__device__ __nv_bfloat16 g_xs_hi[CDIM*CDIM], g_xs_lo[CDIM*CDIM];
__device__ __nv_bfloat16 g_am_hi[CDIM*CDIM], g_am_lo[CDIM*CDIM];

// ---------------- PTX helpers ----------------------------------------------
__device__ __forceinline__ uint32_t smem_u32(const void* p) {
    uint32_t a;
    asm("{ .reg .u64 t; cvta.to.shared.u64 t, %1; cvt.u32.u64 %0, t; }" : "=r"(a) : "l"(p));
    return a;
}
__device__ __forceinline__ void cp16(uint32_t dst, const void* src) {
    asm volatile("cp.async.cg.shared.global [%0], [%1], 16;" :: "r"(dst), "l"(src));
}
__device__ __forceinline__ void ldsm4(uint32_t a, uint32_t* r) {
    asm volatile("ldmatrix.sync.aligned.m8n8.x4.shared.b16 {%0,%1,%2,%3}, [%4];"
                 : "=r"(r[0]), "=r"(r[1]), "=r"(r[2]), "=r"(r[3]) : "r"(a));
}
__device__ __forceinline__ void mma16816(float* c, const uint32_t* a, const uint32_t* b) {
    asm volatile("mma.sync.aligned.m16n8k16.row.col.f32.bf16.bf16.f32 "
        "{%0,%1,%2,%3}, {%4,%5,%6,%7}, {%8,%9}, {%0,%1,%2,%3};"
        : "+f"(c[0]), "+f"(c[1]), "+f"(c[2]), "+f"(c[3])
        : "r"(a[0]), "r"(a[1]), "r"(a[2]), "r"(a[3]), "r"(b[0]), "r"(b[1]));
}

// ---------------- HMMA bf16-split GEMM --------------------------------------
// C[M,N] = alpha * (A @ B^T) + beta * Cin. A: MxK row-major, B: NxK row-major,
// K = 1024. A = Ahi+Alo, B = Bhi+Blo. grid = (N/128, M/128), 256 threads.
static constexpr int SSTR   = 72;                 // smem row stride (bf16 elems) = 144B
static constexpr int TILE_BY = 128 * SSTR * 2;    // 18432 bytes per tile
static constexpr int STG_BY  = 4 * TILE_BY;       // Ahi, Alo, Bhi, Blo
static constexpr int GEMM_SMEM = 2 * STG_BY;      // 147456 bytes (double buffered)

__device__ __forceinline__ void load_stage(uint32_t stg,
    const __nv_bfloat16* __restrict__ Ahi, const __nv_bfloat16* __restrict__ Alo,
    const __nv_bfloat16* __restrict__ Bhi, const __nv_bfloat16* __restrict__ Blo,
    int m0, int n0, int k0, int tid)
{
    #pragma unroll
    for (int t = 0; t < 16; t++) {
        int i = tid + t*256;
        int tile = i >> 10;            // 0..3
        int rem  = i & 1023;
        int r    = rem >> 3;           // row 0..127
        int c    = (rem & 7) << 3;     // elem col 0,8,..,56
        uint32_t dst = stg + tile*TILE_BY + r*144 + c*2;
        const __nv_bfloat16* base = (tile == 0) ? Ahi : (tile == 1) ? Alo
                                  : (tile == 2) ? Bhi : Blo;
        int row0 = (tile < 2) ? m0 : n0;
        cp16(dst, base + (long long)(row0 + r)*CDIM + k0 + c);
    }
}

__global__ void __launch_bounds__(256, 1) mma_gemm(
    const __nv_bfloat16* __restrict__ Ahi, const __nv_bfloat16* __restrict__ Alo,
    const __nv_bfloat16* __restrict__ Bhi, const __nv_bfloat16* __restrict__ Blo,
    float* __restrict__ C, const float* __restrict__ Cin,
    int N, float alpha, float beta)
{
    extern __shared__ char smem[];
    const uint32_t sb = smem_u32(smem);
    const int tid = threadIdx.x, wid = tid >> 5, lane = tid & 31;
    const int m0 = blockIdx.y * 128, n0 = blockIdx.x * 128;
    const int warp_m = wid & 3;    // 4 warps along M (32 rows each)
    const int warp_n = wid >> 2;   // 2 warps along N (64 cols each)

    float acc[2][8][4];
    #pragma unroll
    for (int a = 0; a < 2; a++)
        #pragma unroll
        for (int b = 0; b < 8; b++)
            #pragma unroll
            for (int c = 0; c < 4; c++) acc[a][b][c] = 0.0f;

    // per-thread ldmatrix base offsets (tile-local bytes)
    // A (x4): lanes 0-7 -> m0-7/k0-7, 8-15 -> m8-15/k0-7, 16-23 -> m0-7/k8-15, 24-31 -> m8-15/k8-15
    const uint32_t a_base = (warp_m*32 + (lane & 15))*144 + ((lane >> 4) << 4);
    // B (x4, non-trans): lanes 0-7 -> n0-7/k0-7, 8-15 -> n0-7/k8-15, 16-23 -> n8-15/k0-7, 24-31 -> n8-15/k8-15
    const uint32_t b_base = (warp_n*64 + (lane & 7) + ((lane >> 4) << 3))*144
                          + (((lane >> 3) & 1) << 4);

    load_stage(sb, Ahi, Alo, Bhi, Blo, m0, n0, 0, tid);
    asm volatile("cp.async.commit_group;" ::: "memory");

    for (int kt = 0; kt < 16; kt++) {
        const int b = kt & 1;
        if (kt + 1 < 16) {
            load_stage(sb + (b^1)*STG_BY, Ahi, Alo, Bhi, Blo, m0, n0, (kt+1)*64, tid);
            asm volatile("cp.async.commit_group;" ::: "memory");
            asm volatile("cp.async.wait_group 1;" ::: "memory");
        } else {
            asm volatile("cp.async.wait_group 0;" ::: "memory");
        }
        __syncthreads();

        const uint32_t stg = sb + b*STG_BY;
        #pragma unroll
        for (int kc = 0; kc < 4; kc++) {
            uint32_t ah[2][4], al[2][4], bh[4][4], bl[4][4];
            const uint32_t ao = stg + a_base + kc*32;
            ldsm4(ao,                       ah[0]);
            ldsm4(ao + 16*144,              ah[1]);
            ldsm4(ao + TILE_BY,             al[0]);
            ldsm4(ao + TILE_BY + 16*144,    al[1]);
            const uint32_t bo = stg + 2*TILE_BY + b_base + kc*32;
            #pragma unroll
            for (int nt2 = 0; nt2 < 4; nt2++) {
                ldsm4(bo + nt2*16*144,           bh[nt2]);
                ldsm4(bo + TILE_BY + nt2*16*144, bl[nt2]);
            }
            #pragma unroll
            for (int mt = 0; mt < 2; mt++)
                #pragma unroll
                for (int nt = 0; nt < 8; nt++) {
                    const int n2 = nt >> 1, hf = (nt & 1) << 1;
                    mma16816(acc[mt][nt], ah[mt], &bh[n2][hf]);
                    mma16816(acc[mt][nt], ah[mt], &bl[n2][hf]);
                    mma16816(acc[mt][nt], al[mt], &bh[n2][hf]);
                }
        }
        __syncthreads();
    }

    // epilogue: register fragments -> gmem (float2 per half-fragment)
    const int qr = lane >> 2, qc = (lane & 3) << 1;
    #pragma unroll
    for (int mt = 0; mt < 2; mt++) {
        #pragma unroll
        for (int nt = 0; nt < 8; nt++) {
            const int row = m0 + warp_m*32 + mt*16 + qr;
            const int col = n0 + warp_n*64 + nt*8 + qc;
            float* c = acc[mt][nt];
            long long i0 = (long long)row*N + col;
            long long i1 = (long long)(row+8)*N + col;
            float2 o0, o1;
            if (Cin) {
                float2 c0 = *(const float2*)(Cin + i0);
                float2 c1 = *(const float2*)(Cin + i1);
                o0.x = alpha*c[0] + beta*c0.x; o0.y = alpha*c[1] + beta*c0.y;
                o1.x = alpha*c[2] + beta*c1.x; o1.y = alpha*c[3] + beta*c1.y;
            } else {
                o0.x = alpha*c[0]; o0.y = alpha*c[1];
                o1.x = alpha*c[2]; o1.y = alpha*c[3];
            }
            *(float2*)(C + i0) = o0;
            *(float2*)(C + i1) = o1;
        }
    }
}

// ---------------- elementwise / split-conversion kernels --------------------
__global__ void scale_kernel(const float* __restrict__ s, float* __restrict__ d, float f, long long n) {
    long long i = (long long)blockIdx.x*blockDim.x + threadIdx.x;
    if (i < n) d[i] = s[i]*f;
}
__global__ void convert_split(const float* __restrict__ src,
                              __nv_bfloat16* __restrict__ hi, __nv_bfloat16* __restrict__ lo, long long n) {
    long long i = (long long)blockIdx.x*blockDim.x + threadIdx.x;
    if (i >= n) return;
    float x = src[i];
    __nv_bfloat16 h = __float2bfloat16(x);
    hi[i] = h; lo[i] = __float2bfloat16(x - __bfloat162float(h));
}
__global__ void transpose_split(const float* __restrict__ src,
                                __nv_bfloat16* __restrict__ hi, __nv_bfloat16* __restrict__ lo) {
    __shared__ float t[32][33];
    const int bx = blockIdx.x*32, by = blockIdx.y*32;
    const int tx = threadIdx.x, ty = threadIdx.y;  // 32x8
    #pragma unroll
    for (int j = 0; j < 32; j += 8)
        t[ty+j][tx] = src[(long long)(by+ty+j)*CDIM + bx + tx];
    __syncthreads();
    #pragma unroll
    for (int j = 0; j < 32; j += 8) {
        float v = t[tx][ty+j];
        __nv_bfloat16 h = __float2bfloat16(v);
        long long o = (long long)(bx+ty+j)*CDIM + by + tx;
        hi[o] = h; lo[o] = __float2bfloat16(v - __bfloat162float(h));
    }
}
__global__ void shift_add_split(const float* __restrict__ cur, const float* __restrict__ ident,
                                __nv_bfloat16* __restrict__ uhi, __nv_bfloat16* __restrict__ ulo, int d) {
    long long i = (long long)blockIdx.x*blockDim.x + threadIdx.x;
    if (i >= TOT) return;
    long long t = i >> 10;
    int c = (int)(i & 1023);
    int tt = (int)(t % TLEN);
    float leftv = (tt >= d) ? cur[i - (long long)d*CDIM] : ident[c];
    float s = leftv + cur[i];
    __nv_bfloat16 h = __float2bfloat16(s);
    uhi[i] = h; ulo[i] = __float2bfloat16(s - __bfloat162float(h));
}
__global__ void mul_split(const float* __restrict__ a, const float* __restrict__ b,
                          __nv_bfloat16* __restrict__ hi, __nv_bfloat16* __restrict__ lo) {
    long long i = (long long)blockIdx.x*blockDim.x + threadIdx.x;
    if (i >= TOT) return;
    float x = a[i]*b[i];
    __nv_bfloat16 h = __float2bfloat16(x);
    hi[i] = h; lo[i] = __float2bfloat16(x - __bfloat162float(h));
}

// ---------------- combine: tiny 4-lane SDPA + rmsnorm per token -------------
__global__ void combine_kernel(const float* __restrict__ cur, const float* __restrict__ vc,
                               const float* __restrict__ ident, float* __restrict__ nxt, int d) {
    const int t = blockIdx.x, tt = t % TLEN, j = threadIdx.x;
    const float* left  = (tt >= d) ? (cur + (long long)(t-d)*CDIM) : ident;
    const float* right = cur + (long long)t*CDIM;
    const float* vv    = vc  + (long long)t*CDIM;
    float l[4], r[4], w[4];
    #pragma unroll
    for (int i = 0; i < 4; i++) { l[i]=left[i*256+j]; r[i]=right[i*256+j]; w[i]=vv[i*256+j]; }
    __shared__ float red[16][8];
    __shared__ float scores[16];
    __shared__ float scale_s[4];
    const int lane = j & 31, warp = j >> 5;
    #pragma unroll
    for (int q = 0; q < 16; q++) {
        float v = l[q>>2]*r[q&3];
        #pragma unroll
        for (int o = 16; o > 0; o >>= 1) v += __shfl_down_sync(0xffffffffu, v, o);
        if (lane == 0) red[q][warp] = v;
    }
    __syncthreads();
    if (j < 16) {
        float s = 0.f;
        #pragma unroll
        for (int wq = 0; wq < 8; wq++) s += red[j][wq];
        scores[j] = s * 0.0625f;
    }
    __syncthreads();
    float att[4][4];
    #pragma unroll
    for (int a = 0; a < 4; a++) {
        float mx = scores[a*4];
        #pragma unroll
        for (int b = 1; b < 4; b++) mx = fmaxf(mx, scores[a*4+b]);
        float sm = 0.f;
        #pragma unroll
        for (int b = 0; b < 4; b++) { att[a][b] = expf(scores[a*4+b]-mx); sm += att[a][b]; }
        float inv = 1.0f/sm;
        #pragma unroll
        for (int b = 0; b < 4; b++) att[a][b] *= inv;
    }
    float z[4];
    #pragma unroll
    for (int a = 0; a < 4; a++)
        z[a] = att[a][0]*w[0] + att[a][1]*w[1] + att[a][2]*w[2] + att[a][3]*w[3];
    __syncthreads();
    #pragma unroll
    for (int a = 0; a < 4; a++) {
        float v = z[a]*z[a];
        #pragma unroll
        for (int o = 16; o > 0; o >>= 1) v += __shfl_down_sync(0xffffffffu, v, o);
        if (lane == 0) red[a][warp] = v;
    }
    __syncthreads();
    if (j < 4) {
        float s = 0.f;
        #pragma unroll
        for (int wq = 0; wq < 8; wq++) s += red[j][wq];
        scale_s[j] = rsqrtf(s*(1.0f/256.0f) + 1e-8f) / (float)(j+1);
    }
    __syncthreads();
    float* o = nxt + (long long)t*CDIM;
    #pragma unroll
    for (int a = 0; a < 4; a++) o[a*256+j] = l[a] + z[a]*scale_s[a];
}

// ---------------- host orchestration ----------------------------------------
static inline void launch_gemm(const __nv_bfloat16* Ahi, const __nv_bfloat16* Alo,
                               const __nv_bfloat16* Bhi, const __nv_bfloat16* Blo,
                               float* C, const float* Cin, int M, int N,
                               float alpha, float beta)
{
    dim3 grid(N/128, M/128);
    mma_gemm<<<grid, 256, GEMM_SMEM>>>(Ahi, Alo, Bhi, Blo, C, Cin, N, alpha, beta);
}

extern "C" void kernel_launch(void* const* d_in, const int* in_sizes, int n_in,
                              void* d_out, int out_size)
{
    const float* x      = (const float*)d_in[0];
    const float* W_up   = (const float*)d_in[1];
    const float* W_v    = (const float*)d_in[2];
    const float* W_proj = (const float*)d_in[3];
    const float* ident  = (const float*)d_in[4];
    const float* W_raw  = (const float*)d_in[5];
    float* out = (float*)d_out;
    const long long half = (long long)out_size / 2;

    cudaFuncSetAttribute(mma_gemm, cudaFuncAttributeMaxDynamicSharedMemorySize, GEMM_SMEM);

    float *q0,*q1,*vc,*v,*X0,*X1,*Am;
    __nv_bfloat16 *gah,*gal,*gbh,*gbl,*wth,*wtl,*xth,*xtl,*xsh,*xsl,*amh,*aml;
    cudaGetSymbolAddress((void**)&q0, g_q0);
    cudaGetSymbolAddress((void**)&q1, g_q1);
    cudaGetSymbolAddress((void**)&vc, g_vc);
    cudaGetSymbolAddress((void**)&v , g_v );
    cudaGetSymbolAddress((void**)&X0, g_X0);
    cudaGetSymbolAddress((void**)&X1, g_X1);
    cudaGetSymbolAddress((void**)&Am, g_Am);
    cudaGetSymbolAddress((void**)&gah, g_ga_hi); cudaGetSymbolAddress((void**)&gal, g_ga_lo);
    cudaGetSymbolAddress((void**)&gbh, g_gb_hi); cudaGetSymbolAddress((void**)&gbl, g_gb_lo);
    cudaGetSymbolAddress((void**)&wth, g_wt_hi); cudaGetSymbolAddress((void**)&wtl, g_wt_lo);
    cudaGetSymbolAddress((void**)&xth, g_xt_hi); cudaGetSymbolAddress((void**)&xtl, g_xt_lo);
    cudaGetSymbolAddress((void**)&xsh, g_xs_hi); cudaGetSymbolAddress((void**)&xsl, g_xs_lo);
    cudaGetSymbolAddress((void**)&amh, g_am_hi); cudaGetSymbolAddress((void**)&aml, g_am_lo);

    const int C = CDIM;
    const long long WN = (long long)C*C;
    const int wb = (int)((WN + 255)/256);
    const int eb = (int)((TOT + 255)/256);
    dim3 tgrid(32, 32), tblk(32, 8);

    // ---- 1) Newton-Schulz polar: W = polar(W_scan_raw) ----
    scale_kernel<<<wb,256>>>(W_raw, X0, 2.0f/3.0f, WN);
    float* X = X0; float* Xn = X1;
    for (int it = 0; it < NS_ITERS; it++) {
        transpose_split<<<tgrid, tblk>>>(X, xth, xtl);
        launch_gemm(xth, xtl, xth, xtl, Am, nullptr, C, C, 1.0f, 0.0f);   // Am = X^T X
        convert_split<<<wb,256>>>(Am, amh, aml, WN);
        convert_split<<<wb,256>>>(X,  xsh, xsl, WN);
        launch_gemm(xsh, xsl, amh, aml, Xn, X, C, C, -0.5f, 1.5f);        // Xn = 1.5X - 0.5 X Am
        float* tmp = X; X = Xn; Xn = tmp;
    }
    transpose_split<<<tgrid, tblk>>>(X, wth, wtl);                        // W^T for scan

    // ---- 2) q0 = x @ W_up^T ; v = x @ W_v^T ----
    convert_split<<<eb,256>>>(x, gah, gal, TOT);
    convert_split<<<wb,256>>>(W_up, gbh, gbl, WN);
    launch_gemm(gah, gal, gbh, gbl, q0, nullptr, BT, C, 1.0f, 0.0f);
    convert_split<<<wb,256>>>(W_v, gbh, gbl, WN);
    launch_gemm(gah, gal, gbh, gbl, v, nullptr, BT, C, 1.0f, 0.0f);

    // ---- 3) parallel scan: 11 Hillis-Steele steps ----
    float* cur = q0; float* nxt = q1;
    for (int d = 1; d < TLEN; d <<= 1) {
        shift_add_split<<<eb,256>>>(cur, ident, gah, gal, d);
        launch_gemm(gah, gal, wth, wtl, vc, nullptr, BT, C, 1.0f, 0.0f);  // vc = u @ W
        combine_kernel<<<BT,256>>>(cur, vc, ident, nxt, d);
        float* tmp = cur; cur = nxt; nxt = tmp;
    }

    // ---- 4) Y = (q*v) @ W_proj^T ; write (Y, q) ----
    mul_split<<<eb,256>>>(cur, v, gah, gal);
    convert_split<<<wb,256>>>(W_proj, gbh, gbl, WN);
    launch_gemm(gah, gal, gbh, gbl, out, nullptr, BT, C, 1.0f, 0.0f);
    cudaMemcpyAsync(out + half, cur, half*sizeof(float), cudaMemcpyDeviceToDevice, 0);
}

// round 5
// speedup vs baseline: 5.9335x; 1.4918x over previous
#include <cuda_runtime.h>
#include <cuda_bf16.h>
#include <cstdint>
#include <math.h>

#define BSZ 4
#define TLEN 2048
#define CDIM 1024
#define BT (BSZ*TLEN)            // 8192
#define TOT ((long long)BT*CDIM)
#define N2 (CDIM*CDIM)

typedef __nv_bfloat16 bf16;

// ---------------- scratch (device globals; no cudaMalloc allowed) ----------
__device__ float g_q0[BT*CDIM];
__device__ float g_q1[BT*CDIM];
__device__ float g_vc[BT*CDIM];
__device__ float g_v [BT*CDIM];
__device__ float g_X0[N2];
__device__ float g_X1[N2];
__device__ float g_Am[N2];
__device__ bf16 g_ga_hi[BT*CDIM], g_ga_lo[BT*CDIM];     // big A operand splits
__device__ bf16 g_gb_hi[N2], g_gb_lo[N2];               // W_up/W_v/W_proj splits
__device__ bf16 g_xh[2][N2], g_xl[2][N2];               // X splits (ping-pong)
__device__ bf16 g_xth[2][N2], g_xtl[2][N2];             // X^T splits (ping-pong)
__device__ bf16 g_ah[N2], g_al[N2];                     // A = X^T X splits
__device__ bf16 g_sh[N2], g_sl[N2];                     // S splits

// ---------------- PTX helpers ----------------------------------------------
__device__ __forceinline__ uint32_t smem_u32(const void* p) {
    uint32_t a;
    asm("{ .reg .u64 t; cvta.to.shared.u64 t, %1; cvt.u32.u64 %0, t; }" : "=r"(a) : "l"(p));
    return a;
}
__device__ __forceinline__ void cp16(uint32_t dst, const void* src) {
    asm volatile("cp.async.cg.shared.global [%0], [%1], 16;" :: "r"(dst), "l"(src));
}
__device__ __forceinline__ void ldsm4(uint32_t a, uint32_t* r) {
    asm volatile("ldmatrix.sync.aligned.m8n8.x4.shared.b16 {%0,%1,%2,%3}, [%4];"
                 : "=r"(r[0]), "=r"(r[1]), "=r"(r[2]), "=r"(r[3]) : "r"(a));
}
__device__ __forceinline__ void mma16816(float* c, const uint32_t* a, const uint32_t* b) {
    asm volatile("mma.sync.aligned.m16n8k16.row.col.f32.bf16.bf16.f32 "
        "{%0,%1,%2,%3}, {%4,%5,%6,%7}, {%8,%9}, {%0,%1,%2,%3};"
        : "+f"(c[0]), "+f"(c[1]), "+f"(c[2]), "+f"(c[3])
        : "r"(a[0]), "r"(a[1]), "r"(a[2]), "r"(a[3]), "r"(b[0]), "r"(b[1]));
}

// ---------------- HMMA bf16-split GEMM --------------------------------------
// C[M,N] = alpha * (A @ B^T) + beta * Cin. A: MxK row-major, B: NxK row-major,
// K = 1024. A = Ahi+Alo, B = Bhi+Blo (3-product fp32 emulation).
// Optional epilogue outputs: Cout fp32, Chi/Clo bf16 split, CThi/CTlo transposed split.
// grid = (N/BN, M/128), 256 threads, 3-stage cp.async pipeline.
template<int BN>
__device__ __forceinline__ void load_stage_t(uint32_t stg,
    const bf16* __restrict__ Ahi, const bf16* __restrict__ Alo,
    const bf16* __restrict__ Bhi, const bf16* __restrict__ Blo,
    int m0, int n0, int k0, int tid)
{
    constexpr int TILE_A_BY = 128*144;
    constexpr int TILE_B_BY = BN*144;
    constexpr int ITERS = (256 + 2*BN)*8/256;
    #pragma unroll
    for (int t = 0; t < ITERS; t++) {
        int i = tid + t*256;
        int r_all = i >> 3;
        int c = (i & 7) << 3;
        uint32_t dst; const bf16* src;
        if (r_all < 128) {
            dst = stg + r_all*144 + c*2;
            src = Ahi + (long long)(m0+r_all)*CDIM + k0 + c;
        } else if (r_all < 256) {
            int r = r_all - 128;
            dst = stg + TILE_A_BY + r*144 + c*2;
            src = Alo + (long long)(m0+r)*CDIM + k0 + c;
        } else if (r_all < 256+BN) {
            int r = r_all - 256;
            dst = stg + 2*TILE_A_BY + r*144 + c*2;
            src = Bhi + (long long)(n0+r)*CDIM + k0 + c;
        } else {
            int r = r_all - 256 - BN;
            dst = stg + 2*TILE_A_BY + TILE_B_BY + r*144 + c*2;
            src = Blo + (long long)(n0+r)*CDIM + k0 + c;
        }
        cp16(dst, src);
    }
}

template<int BN>
__global__ void __launch_bounds__(256, 1) mma_gemm(
    const bf16* __restrict__ Ahi, const bf16* __restrict__ Alo,
    const bf16* __restrict__ Bhi, const bf16* __restrict__ Blo,
    float* __restrict__ Cout, const float* __restrict__ Cin,
    bf16* __restrict__ Chi, bf16* __restrict__ Clo,
    bf16* __restrict__ CThi, bf16* __restrict__ CTlo,
    int M, int N, float alpha, float beta)
{
    constexpr int TILE_A_BY = 128*144;
    constexpr int TILE_B_BY = BN*144;
    constexpr int STG_BY = 2*TILE_A_BY + 2*TILE_B_BY;
    constexpr int NT2 = BN/32;       // 16-row B ldsm groups per warp
    constexpr int NTT = BN/16;       // 8-col mma fragments per warp
    constexpr int WROWS = BN/2;      // B rows per warp_n

    extern __shared__ char smem[];
    const uint32_t sb = smem_u32(smem);
    const int tid = threadIdx.x, wid = tid >> 5, lane = tid & 31;
    const int m0 = blockIdx.y * 128, n0 = blockIdx.x * BN;
    const int warp_m = wid & 3;
    const int warp_n = wid >> 2;

    float acc[2][NTT][4];
    #pragma unroll
    for (int a = 0; a < 2; a++)
        #pragma unroll
        for (int b = 0; b < NTT; b++)
            #pragma unroll
            for (int c = 0; c < 4; c++) acc[a][b][c] = 0.0f;

    const uint32_t a_base = (warp_m*32 + (lane & 15))*144 + ((lane >> 4) << 4);
    const uint32_t b_base = (warp_n*WROWS + (lane & 7) + ((lane >> 4) << 3))*144
                          + (((lane >> 3) & 1) << 4);

    // prologue: stages 0,1
    load_stage_t<BN>(sb, Ahi, Alo, Bhi, Blo, m0, n0, 0, tid);
    asm volatile("cp.async.commit_group;" ::: "memory");
    load_stage_t<BN>(sb + STG_BY, Ahi, Alo, Bhi, Blo, m0, n0, 64, tid);
    asm volatile("cp.async.commit_group;" ::: "memory");

    for (int kt = 0; kt < 16; kt++) {
        __syncthreads();
        if (kt + 2 < 16) {
            load_stage_t<BN>(sb + ((kt+2)%3)*STG_BY, Ahi, Alo, Bhi, Blo, m0, n0, (kt+2)*64, tid);
            asm volatile("cp.async.commit_group;" ::: "memory");
        }
        if (kt < 14)       asm volatile("cp.async.wait_group 2;" ::: "memory");
        else if (kt == 14) asm volatile("cp.async.wait_group 1;" ::: "memory");
        else               asm volatile("cp.async.wait_group 0;" ::: "memory");
        __syncthreads();

        const uint32_t stg = sb + (kt%3)*STG_BY;
        #pragma unroll
        for (int kc = 0; kc < 4; kc++) {
            uint32_t ah[2][4], al[2][4], bh[NT2][4], bl[NT2][4];
            const uint32_t ao = stg + a_base + kc*32;
            ldsm4(ao,                       ah[0]);
            ldsm4(ao + 16*144,              ah[1]);
            ldsm4(ao + TILE_A_BY,           al[0]);
            ldsm4(ao + TILE_A_BY + 16*144,  al[1]);
            const uint32_t bo = stg + 2*TILE_A_BY + b_base + kc*32;
            #pragma unroll
            for (int nt2 = 0; nt2 < NT2; nt2++) {
                ldsm4(bo + nt2*16*144,             bh[nt2]);
                ldsm4(bo + TILE_B_BY + nt2*16*144, bl[nt2]);
            }
            #pragma unroll
            for (int mt = 0; mt < 2; mt++)
                #pragma unroll
                for (int nt = 0; nt < NTT; nt++) {
                    const int n2 = nt >> 1, hf = (nt & 1) << 1;
                    mma16816(acc[mt][nt], ah[mt], &bh[n2][hf]);
                    mma16816(acc[mt][nt], ah[mt], &bl[n2][hf]);
                    mma16816(acc[mt][nt], al[mt], &bh[n2][hf]);
                }
        }
    }
    __syncthreads();   // smem free for epilogue staging

    // ---- epilogue ----
    constexpr int STRD = BN + 5;       // float stride for transpose staging
    float* st = (float*)smem;
    const bool doCT = (CThi != nullptr);
    const int qr = lane >> 2, qc = (lane & 3) << 1;

    #pragma unroll
    for (int mt = 0; mt < 2; mt++) {
        #pragma unroll
        for (int nt = 0; nt < NTT; nt++) {
            const int lr = warp_m*32 + mt*16 + qr;
            const int lc = warp_n*WROWS + nt*8 + qc;
            const int row = m0 + lr, col = n0 + lc;
            float* c = acc[mt][nt];
            const long long i0 = (long long)row*N + col;
            const long long i1 = (long long)(row+8)*N + col;
            float v0 = alpha*c[0], v1 = alpha*c[1], v2 = alpha*c[2], v3 = alpha*c[3];
            if (Cin) {
                float2 c0 = *(const float2*)(Cin + i0);
                float2 c1 = *(const float2*)(Cin + i1);
                v0 += beta*c0.x; v1 += beta*c0.y; v2 += beta*c1.x; v3 += beta*c1.y;
            }
            if (Cout) {
                *(float2*)(Cout + i0) = make_float2(v0, v1);
                *(float2*)(Cout + i1) = make_float2(v2, v3);
            }
            if (Chi) {
                bf16 h0 = __float2bfloat16(v0), h1 = __float2bfloat16(v1);
                bf16 h2 = __float2bfloat16(v2), h3 = __float2bfloat16(v3);
                *(__nv_bfloat162*)(Chi + i0) = __nv_bfloat162(h0, h1);
                *(__nv_bfloat162*)(Chi + i1) = __nv_bfloat162(h2, h3);
                *(__nv_bfloat162*)(Clo + i0) = __nv_bfloat162(
                    __float2bfloat16(v0 - __bfloat162float(h0)),
                    __float2bfloat16(v1 - __bfloat162float(h1)));
                *(__nv_bfloat162*)(Clo + i1) = __nv_bfloat162(
                    __float2bfloat16(v2 - __bfloat162float(h2)),
                    __float2bfloat16(v3 - __bfloat162float(h3)));
            }
            if (doCT) {
                st[lr*STRD + lc]     = v0;
                st[lr*STRD + lc+1]   = v1;
                st[(lr+8)*STRD + lc]   = v2;
                st[(lr+8)*STRD + lc+1] = v3;
            }
        }
    }
    if (doCT) {
        __syncthreads();
        // write transposed splits: CT[(n0+n)*M + m0+m] = tile[m][n]
        for (int idx = tid; idx < BN*64; idx += 256) {
            const int n = idx >> 6;
            const int m = (idx & 63) << 1;
            float v0 = st[m*STRD + n];
            float v1 = st[(m+1)*STRD + n];
            bf16 h0 = __float2bfloat16(v0), h1 = __float2bfloat16(v1);
            const long long o = (long long)(n0+n)*M + (m0+m);
            *(__nv_bfloat162*)(CThi + o) = __nv_bfloat162(h0, h1);
            *(__nv_bfloat162*)(CTlo + o) = __nv_bfloat162(
                __float2bfloat16(v0 - __bfloat162float(h0)),
                __float2bfloat16(v1 - __bfloat162float(h1)));
        }
    }
}

static constexpr int SMEM_BIG = 3*(2*128*144 + 2*128*144);   // 221184
static constexpr int SMEM_NS  = 3*(2*128*144 + 2*64*144);    // 165888

// ---------------- elementwise kernels ----------------------------------------
__global__ void convert_split(const float* __restrict__ src,
                              bf16* __restrict__ hi, bf16* __restrict__ lo, long long n) {
    long long i = (long long)blockIdx.x*blockDim.x + threadIdx.x;
    if (i >= n) return;
    float x = src[i];
    bf16 h = __float2bfloat16(x);
    hi[i] = h; lo[i] = __float2bfloat16(x - __bfloat162float(h));
}
// X0 = scale*Wraw; write fp32, splits, transposed splits
__global__ void init_X(const float* __restrict__ src, float scale, float* __restrict__ X,
                       bf16* __restrict__ xh, bf16* __restrict__ xl,
                       bf16* __restrict__ xth, bf16* __restrict__ xtl) {
    __shared__ float t[32][33];
    const int bx = blockIdx.x*32, by = blockIdx.y*32;
    const int tx = threadIdx.x, ty = threadIdx.y;  // 32x8
    #pragma unroll
    for (int j = 0; j < 32; j += 8) {
        long long o = (long long)(by+ty+j)*CDIM + bx + tx;
        float v = src[o]*scale;
        X[o] = v;
        bf16 h = __float2bfloat16(v);
        xh[o] = h; xl[o] = __float2bfloat16(v - __bfloat162float(h));
        t[ty+j][tx] = v;
    }
    __syncthreads();
    #pragma unroll
    for (int j = 0; j < 32; j += 8) {
        float v = t[tx][ty+j];
        bf16 h = __float2bfloat16(v);
        long long o = (long long)(bx+ty+j)*CDIM + by + tx;
        xth[o] = h; xtl[o] = __float2bfloat16(v - __bfloat162float(h));
    }
}
__global__ void shift_add_split(const float* __restrict__ cur, const float* __restrict__ ident,
                                bf16* __restrict__ uhi, bf16* __restrict__ ulo, int d) {
    long long i = (long long)blockIdx.x*blockDim.x + threadIdx.x;
    if (i >= TOT) return;
    long long t = i >> 10;
    int c = (int)(i & 1023);
    int tt = (int)(t % TLEN);
    float leftv = (tt >= d) ? cur[i - (long long)d*CDIM] : ident[c];
    float s = leftv + cur[i];
    bf16 h = __float2bfloat16(s);
    uhi[i] = h; ulo[i] = __float2bfloat16(s - __bfloat162float(h));
}
__global__ void mul_split(const float* __restrict__ a, const float* __restrict__ b,
                          bf16* __restrict__ hi, bf16* __restrict__ lo) {
    long long i = (long long)blockIdx.x*blockDim.x + threadIdx.x;
    if (i >= TOT) return;
    float x = a[i]*b[i];
    bf16 h = __float2bfloat16(x);
    hi[i] = h; lo[i] = __float2bfloat16(x - __bfloat162float(h));
}

// ---------------- combine: tiny 4-lane SDPA + rmsnorm per token -------------
__global__ void combine_kernel(const float* __restrict__ cur, const float* __restrict__ vc,
                               const float* __restrict__ ident, float* __restrict__ nxt, int d) {
    const int t = blockIdx.x, tt = t % TLEN, j = threadIdx.x;
    const float* left  = (tt >= d) ? (cur + (long long)(t-d)*CDIM) : ident;
    const float* right = cur + (long long)t*CDIM;
    const float* vv    = vc  + (long long)t*CDIM;
    float l[4], r[4], w[4];
    #pragma unroll
    for (int i = 0; i < 4; i++) { l[i]=left[i*256+j]; r[i]=right[i*256+j]; w[i]=vv[i*256+j]; }
    __shared__ float red[16][8];
    __shared__ float scores[16];
    __shared__ float scale_s[4];
    const int lane = j & 31, warp = j >> 5;
    #pragma unroll
    for (int q = 0; q < 16; q++) {
        float v = l[q>>2]*r[q&3];
        #pragma unroll
        for (int o = 16; o > 0; o >>= 1) v += __shfl_down_sync(0xffffffffu, v, o);
        if (lane == 0) red[q][warp] = v;
    }
    __syncthreads();
    if (j < 16) {
        float s = 0.f;
        #pragma unroll
        for (int wq = 0; wq < 8; wq++) s += red[j][wq];
        scores[j] = s * 0.0625f;
    }
    __syncthreads();
    float att[4][4];
    #pragma unroll
    for (int a = 0; a < 4; a++) {
        float mx = scores[a*4];
        #pragma unroll
        for (int b = 1; b < 4; b++) mx = fmaxf(mx, scores[a*4+b]);
        float sm = 0.f;
        #pragma unroll
        for (int b = 0; b < 4; b++) { att[a][b] = expf(scores[a*4+b]-mx); sm += att[a][b]; }
        float inv = 1.0f/sm;
        #pragma unroll
        for (int b = 0; b < 4; b++) att[a][b] *= inv;
    }
    float z[4];
    #pragma unroll
    for (int a = 0; a < 4; a++)
        z[a] = att[a][0]*w[0] + att[a][1]*w[1] + att[a][2]*w[2] + att[a][3]*w[3];
    __syncthreads();
    #pragma unroll
    for (int a = 0; a < 4; a++) {
        float v = z[a]*z[a];
        #pragma unroll
        for (int o = 16; o > 0; o >>= 1) v += __shfl_down_sync(0xffffffffu, v, o);
        if (lane == 0) red[a][warp] = v;
    }
    __syncthreads();
    if (j < 4) {
        float s = 0.f;
        #pragma unroll
        for (int wq = 0; wq < 8; wq++) s += red[j][wq];
        scale_s[j] = rsqrtf(s*(1.0f/256.0f) + 1e-8f) / (float)(j+1);
    }
    __syncthreads();
    float* o = nxt + (long long)t*CDIM;
    #pragma unroll
    for (int a = 0; a < 4; a++) o[a*256+j] = l[a] + z[a]*scale_s[a];
}

// ---------------- host orchestration ----------------------------------------
static inline void gemmBig(const bf16* Ahi, const bf16* Alo, const bf16* Bhi, const bf16* Blo,
                           float* Cout, const float* Cin, int M, int N, float alpha, float beta)
{
    dim3 grid(N/128, M/128);
    mma_gemm<128><<<grid, 256, SMEM_BIG>>>(Ahi, Alo, Bhi, Blo, Cout, Cin,
                                           nullptr, nullptr, nullptr, nullptr, M, N, alpha, beta);
}
static inline void gemmNS(const bf16* Ahi, const bf16* Alo, const bf16* Bhi, const bf16* Blo,
                          float* Cout, const float* Cin,
                          bf16* Chi, bf16* Clo, bf16* CThi, bf16* CTlo,
                          float alpha, float beta)
{
    dim3 grid(CDIM/64, CDIM/128);
    mma_gemm<64><<<grid, 256, SMEM_NS>>>(Ahi, Alo, Bhi, Blo, Cout, Cin,
                                         Chi, Clo, CThi, CTlo, CDIM, CDIM, alpha, beta);
}

extern "C" void kernel_launch(void* const* d_in, const int* in_sizes, int n_in,
                              void* d_out, int out_size)
{
    const float* x      = (const float*)d_in[0];
    const float* W_up   = (const float*)d_in[1];
    const float* W_v    = (const float*)d_in[2];
    const float* W_proj = (const float*)d_in[3];
    const float* ident  = (const float*)d_in[4];
    const float* W_raw  = (const float*)d_in[5];
    float* out = (float*)d_out;
    const long long half = (long long)out_size / 2;

    cudaFuncSetAttribute(mma_gemm<128>, cudaFuncAttributeMaxDynamicSharedMemorySize, SMEM_BIG);
    cudaFuncSetAttribute(mma_gemm<64>,  cudaFuncAttributeMaxDynamicSharedMemorySize, SMEM_NS);

    float *q0,*q1,*vc,*v,*X0,*X1,*Am;
    bf16 *gah,*gal,*gbh,*gbl,*ah,*al,*sh,*sl;
    bf16 *xh[2],*xl[2],*xth[2],*xtl[2];
    cudaGetSymbolAddress((void**)&q0, g_q0);
    cudaGetSymbolAddress((void**)&q1, g_q1);
    cudaGetSymbolAddress((void**)&vc, g_vc);
    cudaGetSymbolAddress((void**)&v , g_v );
    cudaGetSymbolAddress((void**)&X0, g_X0);
    cudaGetSymbolAddress((void**)&X1, g_X1);
    cudaGetSymbolAddress((void**)&Am, g_Am);
    cudaGetSymbolAddress((void**)&gah, g_ga_hi); cudaGetSymbolAddress((void**)&gal, g_ga_lo);
    cudaGetSymbolAddress((void**)&gbh, g_gb_hi); cudaGetSymbolAddress((void**)&gbl, g_gb_lo);
    cudaGetSymbolAddress((void**)&ah, g_ah); cudaGetSymbolAddress((void**)&al, g_al);
    cudaGetSymbolAddress((void**)&sh, g_sh); cudaGetSymbolAddress((void**)&sl, g_sl);
    { bf16* p; cudaGetSymbolAddress((void**)&p, g_xh);  xh[0]=p;  xh[1]=p+N2; }
    { bf16* p; cudaGetSymbolAddress((void**)&p, g_xl);  xl[0]=p;  xl[1]=p+N2; }
    { bf16* p; cudaGetSymbolAddress((void**)&p, g_xth); xth[0]=p; xth[1]=p+N2; }
    { bf16* p; cudaGetSymbolAddress((void**)&p, g_xtl); xtl[0]=p; xtl[1]=p+N2; }

    const long long WN = (long long)N2;
    const int wb = (int)((WN + 255)/256);
    const int eb = (int)((TOT + 255)/256);
    dim3 tgrid(32, 32), tblk(32, 8);

    // ---- 1) polar factor via quintic (Muon) + cubic polish ----
    // X0 = Wraw/1.35 : sigma in [~3.5e-4, ~0.95]
    init_X<<<tgrid, tblk>>>(W_raw, 1.0f/1.35f, X0, xh[0], xl[0], xth[0], xtl[0]);
    float* Xc = X0; float* Xn = X1;
    int pp = 0;
    const float qa = 3.4445f, qb = -4.7750f, qc5 = 2.0315f;
    for (int it = 0; it < 9; it++) {
        // A = X^T X  (fp32 + splits)
        gemmNS(xth[pp], xtl[pp], xth[pp], xtl[pp], Am, nullptr,
               ah, al, nullptr, nullptr, 1.0f, 0.0f);
        // S = qc5 * A@A + qb * A  (splits only; S symmetric)
        gemmNS(ah, al, ah, al, nullptr, Am,
               sh, sl, nullptr, nullptr, qc5, qb);
        // Xn = X @ S + qa * X  (fp32 + splits + transposed splits)
        gemmNS(xh[pp], xl[pp], sh, sl, Xn, Xc,
               xh[pp^1], xl[pp^1], xth[pp^1], xtl[pp^1], 1.0f, qa);
        float* tmp = Xc; Xc = Xn; Xn = tmp; pp ^= 1;
    }
    for (int it = 0; it < 4; it++) {
        // A = X^T X (splits only)
        gemmNS(xth[pp], xtl[pp], xth[pp], xtl[pp], nullptr, nullptr,
               ah, al, nullptr, nullptr, 1.0f, 0.0f);
        // Xn = -0.5 * X@A + 1.5 * X
        gemmNS(xh[pp], xl[pp], ah, al, Xn, Xc,
               xh[pp^1], xl[pp^1], xth[pp^1], xtl[pp^1], -0.5f, 1.5f);
        float* tmp = Xc; Xc = Xn; Xn = tmp; pp ^= 1;
    }
    bf16* wth = xth[pp];   // W^T splits for scan (vc = u @ W, NT form)
    bf16* wtl = xtl[pp];

    // ---- 2) q0 = x @ W_up^T ; v = x @ W_v^T ----
    convert_split<<<eb,256>>>(x, gah, gal, TOT);
    convert_split<<<wb,256>>>(W_up, gbh, gbl, WN);
    gemmBig(gah, gal, gbh, gbl, q0, nullptr, BT, CDIM, 1.0f, 0.0f);
    convert_split<<<wb,256>>>(W_v, gbh, gbl, WN);
    gemmBig(gah, gal, gbh, gbl, v, nullptr, BT, CDIM, 1.0f, 0.0f);

    // ---- 3) parallel scan: 11 Hillis-Steele steps ----
    float* cur = q0; float* nxt = q1;
    for (int d = 1; d < TLEN; d <<= 1) {
        shift_add_split<<<eb,256>>>(cur, ident, gah, gal, d);
        gemmBig(gah, gal, wth, wtl, vc, nullptr, BT, CDIM, 1.0f, 0.0f);
        combine_kernel<<<BT,256>>>(cur, vc, ident, nxt, d);
        float* tmp = cur; cur = nxt; nxt = tmp;
    }

    // ---- 4) Y = (q*v) @ W_proj^T ; write (Y, q) ----
    mul_split<<<eb,256>>>(cur, v, gah, gal);
    convert_split<<<wb,256>>>(W_proj, gbh, gbl, WN);
    gemmBig(gah, gal, gbh, gbl, out, nullptr, BT, CDIM, 1.0f, 0.0f);
    cudaMemcpyAsync(out + half, cur, half*sizeof(float), cudaMemcpyDeviceToDevice, 0);
}